// round 2
// baseline (speedup 1.0000x reference)
#include <cuda_runtime.h>
#include <cstdint>

// Problem dims
#define B_N 64
#define T_T 512
#define V_V 25
#define C_IN 3
#define C_H 64
#define F_F 25
#define G_G 100   // 4*F

// Scratch (device globals; no allocation allowed)
__device__ float g_zx[(size_t)T_T * B_N * V_V * G_G];   // [t][n][v][g], zx = relu(x@Wc+bc)@Wl + bl
__device__ float g_hs[(size_t)B_N * T_T * V_V * F_F];   // [n][t][v][f]

__device__ __forceinline__ uint32_t f2tf32(float f) {
    uint32_t u;
    asm("cvt.rna.tf32.f32 %0, %1;" : "=r"(u) : "f"(f));
    return u;
}

__device__ __forceinline__ void mma_tf32(float* d, const uint32_t* a, const uint32_t* b) {
    asm volatile(
        "mma.sync.aligned.m16n8k8.row.col.f32.tf32.tf32.f32 "
        "{%0,%1,%2,%3}, {%4,%5,%6,%7}, {%8,%9}, {%0,%1,%2,%3};\n"
        : "+f"(d[0]), "+f"(d[1]), "+f"(d[2]), "+f"(d[3])
        : "r"(a[0]), "r"(a[1]), "r"(a[2]), "r"(a[3]), "r"(b[0]), "r"(b[1]));
}

__device__ __forceinline__ float hsig(float x) {
    return __saturatef(fmaf(0.2f, x, 0.5f));
}

// ---------------------------------------------------------------------------
// Kernel 1: zx[t,n,v,:] = relu(x[n,t,v,:] @ Wc + bc) @ Wl + bl
// GEMM M=819200, K=64, N=100 via tf32 mma.sync with hi/lo split (3 MMAs) for
// near-fp32 accuracy. A (=x1) is computed on the fly from x; never stored.
// Block: 128 threads (4 warps), tile 64 rows x 104 cols (13 n-tiles of 8).
// ---------------------------------------------------------------------------
__global__ __launch_bounds__(128) void k_zx(
    const float* __restrict__ x, const float* __restrict__ Wc,
    const float* __restrict__ bc, const float* __restrict__ Wl,
    const float* __restrict__ bl)
{
    __shared__ float s_B[64 * 104];   // W_lstm, zero-padded cols 100..103; reused as epilogue staging
    const int tid = threadIdx.x;

    for (int i = tid; i < 64 * 104; i += 128) {
        int k = i / 104, n = i - (i / 104) * 104;
        s_B[i] = (n < G_G) ? Wl[k * G_G + n] : 0.f;
    }
    __syncthreads();

    const int lane = tid & 31, warp = tid >> 5;
    const int gid = lane >> 2;      // groupID
    const int tig = lane & 3;       // threadID in group
    const int rloc0 = warp * 16 + gid;
    const int r0 = blockIdx.x * 64 + rloc0;
    const int r1 = r0 + 8;

    const float x00 = x[r0 * 3 + 0], x01 = x[r0 * 3 + 1], x02 = x[r0 * 3 + 2];
    const float x10 = x[r1 * 3 + 0], x11 = x[r1 * 3 + 1], x12 = x[r1 * 3 + 2];

    float acc[13][4];
#pragma unroll
    for (int i = 0; i < 13; i++) {
#pragma unroll
        for (int j = 0; j < 4; j++) acc[i][j] = 0.f;
    }

#pragma unroll
    for (int kt = 0; kt < 8; kt++) {
        const int c0 = kt * 8 + tig, c1 = c0 + 4;
        // A fragment: x1 = relu(x @ Wc + bc), computed on the fly
        float a00 = fmaxf(fmaf(x02, Wc[128 + c0], fmaf(x01, Wc[64 + c0], fmaf(x00, Wc[c0], bc[c0]))), 0.f);
        float a10 = fmaxf(fmaf(x12, Wc[128 + c0], fmaf(x11, Wc[64 + c0], fmaf(x10, Wc[c0], bc[c0]))), 0.f);
        float a01 = fmaxf(fmaf(x02, Wc[128 + c1], fmaf(x01, Wc[64 + c1], fmaf(x00, Wc[c1], bc[c1]))), 0.f);
        float a11 = fmaxf(fmaf(x12, Wc[128 + c1], fmaf(x11, Wc[64 + c1], fmaf(x10, Wc[c1], bc[c1]))), 0.f);

        uint32_t ah[4], al[4];
        ah[0] = f2tf32(a00); al[0] = __float_as_uint(a00 - __uint_as_float(ah[0]));
        ah[1] = f2tf32(a10); al[1] = __float_as_uint(a10 - __uint_as_float(ah[1]));
        ah[2] = f2tf32(a01); al[2] = __float_as_uint(a01 - __uint_as_float(ah[2]));
        ah[3] = f2tf32(a11); al[3] = __float_as_uint(a11 - __uint_as_float(ah[3]));

        const int br0 = (kt * 8 + tig) * 104 + gid;
        const int br1 = (kt * 8 + tig + 4) * 104 + gid;
#pragma unroll
        for (int nt = 0; nt < 13; nt++) {
            float b0f = s_B[br0 + nt * 8];
            float b1f = s_B[br1 + nt * 8];
            uint32_t bh[2], blo[2];
            bh[0] = f2tf32(b0f); blo[0] = __float_as_uint(b0f - __uint_as_float(bh[0]));
            bh[1] = f2tf32(b1f); blo[1] = __float_as_uint(b1f - __uint_as_float(bh[1]));
            mma_tf32(acc[nt], ah, bh);    // hi*hi
            mma_tf32(acc[nt], ah, blo);   // hi*lo
            mma_tf32(acc[nt], al, bh);    // lo*hi  (lo*lo ~2^-22, negligible)
        }
    }

    __syncthreads();   // everyone done reading s_B; reuse as output staging
#pragma unroll
    for (int nt = 0; nt < 13; nt++) {
        const int cc = nt * 8 + 2 * tig;
        s_B[rloc0 * 104 + cc]           = acc[nt][0];
        s_B[rloc0 * 104 + cc + 1]       = acc[nt][1];
        s_B[(rloc0 + 8) * 104 + cc]     = acc[nt][2];
        s_B[(rloc0 + 8) * 104 + cc + 1] = acc[nt][3];
    }
    __syncthreads();

    const int pbase = blockIdx.x * 64;
    for (int i = tid; i < 64 * G_G; i += 128) {
        int r = i / G_G, g = i - r * G_G;
        int p = pbase + r;                       // p = (n*T + t)*V + v
        int n = p / (T_T * V_V);
        int t = (p / V_V) % T_T;
        int v = p % V_V;
        g_zx[((size_t)(t * B_N + n) * V_V + v) * G_G + g] = s_B[r * 104 + g] + bl[g];
    }
}

// ---------------------------------------------------------------------------
// Kernel 2: LSTM recurrence. One block per (n,v) cell; threads 0..99 each own
// one gate output; threads 0..24 own cell state c_j. Serial over T=512.
// ---------------------------------------------------------------------------
__global__ __launch_bounds__(128) void k_rec(const float* __restrict__ U)
{
    __shared__ float s_U[F_F * G_G];   // 25 x 100
    __shared__ float s_h[F_F];
    __shared__ float s_g[G_G];

    const int tid = threadIdx.x;
    for (int i = tid; i < F_F * G_G; i += 128) s_U[i] = U[i];
    if (tid < F_F) s_h[tid] = 0.f;
    __syncthreads();

    const int n = blockIdx.x / V_V;
    const int v = blockIdx.x % V_V;
    const float* zxp = g_zx + ((size_t)(n * V_V + v)) * G_G;          // + t*B_N*V_V*G_G
    float* hp = g_hs + (size_t)n * T_T * V_V * F_F + (size_t)v * F_F; // + t*V_V*F_F

    float c = 0.f;
    for (int t = 0; t < T_T; t++) {
        if (tid < G_G) {
            float acc = zxp[(size_t)t * (B_N * V_V * G_G) + tid];
#pragma unroll
            for (int j = 0; j < F_F; j++)
                acc = fmaf(s_h[j], s_U[j * G_G + tid], acc);
            s_g[tid] = acc;
        }
        __syncthreads();
        if (tid < F_F) {
            float gi = s_g[tid];
            float gf = s_g[F_F + tid];
            float gg = s_g[2 * F_F + tid];
            float go = s_g[3 * F_F + tid];
            c = hsig(gf) * c + hsig(gi) * tanhf(gg);
            float h = hsig(go) * tanhf(c);
            s_h[tid] = h;
            hp[(size_t)t * (V_V * F_F) + tid] = h;
        }
        __syncthreads();
    }
}

// ---------------------------------------------------------------------------
// Kernel 3: attention softmax + aggregation, one block per (n,t).
// x1 recomputed from x (3 MACs/elem) — avoids re-reading a 210MB x1 buffer.
// out[v,c] = sum_w softmax_w(leaky(h[v,w]) + bias[v,w]) * x1[w,c]
// ---------------------------------------------------------------------------
__global__ __launch_bounds__(256) void k_agg(
    const float* __restrict__ x, const float* __restrict__ Wc,
    const float* __restrict__ bc, const float* __restrict__ bias,
    float* __restrict__ out)
{
    __shared__ float s_x1[V_V * C_H];    // 25 x 64
    __shared__ float s_hr[V_V * F_F];    // 25 x 25
    __shared__ float s_co[V_V * F_F];    // coefs

    const int b = blockIdx.x;            // n*T + t
    const int tid = threadIdx.x;

    const float* xp = x + (size_t)b * V_V * C_IN;
    for (int i = tid; i < V_V * C_H; i += 256) {
        int v = i >> 6, cch = i & 63;
        float val = fmaf(xp[v * 3 + 2], Wc[128 + cch],
                    fmaf(xp[v * 3 + 1], Wc[64 + cch],
                    fmaf(xp[v * 3 + 0], Wc[cch], bc[cch])));
        s_x1[i] = fmaxf(val, 0.f);
    }
    const float* hpp = g_hs + (size_t)b * (V_V * F_F);
    for (int i = tid; i < V_V * F_F; i += 256) s_hr[i] = hpp[i];
    __syncthreads();

    if (tid < V_V) {
        const int v = tid;
        float mx = -1e30f;
#pragma unroll
        for (int w = 0; w < F_F; w++) {
            float h = s_hr[v * F_F + w];
            float l = (h > 0.f ? h : 0.2f * h) + bias[v * V_V + w];
            s_co[v * F_F + w] = l;
            mx = fmaxf(mx, l);
        }
        float s = 0.f;
#pragma unroll
        for (int w = 0; w < F_F; w++) {
            float e = expf(s_co[v * F_F + w] - mx);
            s_co[v * F_F + w] = e;
            s += e;
        }
        float inv = 1.f / s;
#pragma unroll
        for (int w = 0; w < F_F; w++) s_co[v * F_F + w] *= inv;
    }
    __syncthreads();

    float* op = out + (size_t)b * V_V * C_H;
    for (int i = tid; i < V_V * C_H; i += 256) {
        int v = i >> 6, cch = i & 63;
        float acc = 0.f;
#pragma unroll
        for (int w = 0; w < F_F; w++)
            acc = fmaf(s_co[v * F_F + w], s_x1[w * C_H + cch], acc);
        op[i] = acc;
    }
}

// ---------------------------------------------------------------------------
extern "C" void kernel_launch(void* const* d_in, const int* in_sizes, int n_in,
                              void* d_out, int out_size)
{
    const float* x    = (const float*)d_in[0];   // (64,512,25,3)
    const float* Wc   = (const float*)d_in[1];   // (3,64)
    const float* bc   = (const float*)d_in[2];   // (64,)
    const float* Wl   = (const float*)d_in[3];   // (64,100)
    const float* Ul   = (const float*)d_in[4];   // (25,100)
    const float* bl   = (const float*)d_in[5];   // (100,)
    const float* bias = (const float*)d_in[6];   // (25,25)
    float* out = (float*)d_out;                  // (64,512,25,64)

    k_zx<<<(B_N * T_T * V_V) / 64, 128>>>(x, Wc, bc, Wl, bl);
    k_rec<<<B_N * V_V, 128>>>(Ul);
    k_agg<<<B_N * T_T, 256>>>(x, Wc, bc, bias, out);
}